// round 9
// baseline (speedup 1.0000x reference)
#include <cuda_runtime.h>
#include <cuda_bf16.h>
#include <math.h>
#include <mma.h>
using namespace nvcuda;

#define BB 128
#define SS 50
#define DD 128
#define NNODE 40000
#define SAMP 12
#define NNEI 8
#define LEAKC 0.2f
#define NSCORE 39999

// ---------------- scratch (device globals; no allocation) ----------------
__device__ float g_h[BB*SS*DD];
__device__ float g_hf1[BB*SS*DD];
__device__ float g_hf2[BB*SS*DD];
__device__ float g_x[BB*SS*DD];
__device__ float g_mirror[BB*SS*DD];
__device__ float g_xnew[BB*SS*DD];
__device__ float g_xdot[BB*SS*DD];
__device__ float g_sess[BB*DD];
__device__ float g_out0[BB*SS*DD];
__device__ float g_out1[BB*600*DD];
__device__ float g_hglob[BB*SS*DD];
__device__ float g_hs[BB*DD];
__device__ float g_hlocal[BB*DD];
__device__ float g_c2[BB*DD];
__device__ float g_beta[BB*SS];
__device__ float g_zg[BB*DD];
__device__ float g_zhT[DD*BB];
__device__ float g_partial[BB*SS];
__device__ float g_cat[BB*600*2*DD];    // [rows][256] concat buffer
__device__ float g_logits[BB*7200];     // per-sample attention logits (mode 1)
__device__ __nv_bfloat16 g_w1b[DD*DD];  // W1 (first 128 rows) in bf16

__device__ __forceinline__ float sigm(float x){ return 1.0f/(1.0f+expf(-x)); }

// ---------------- k_w1bf: convert W1[0:128][:] to bf16 ----------------
__global__ void k_w1bf(const float* __restrict__ w1){
  int i = blockIdx.x*256 + threadIdx.x;
  g_w1b[i] = __float2bfloat16(w1[i]);
}

// ---------------- k_pool: h, hf1, hf2 ----------------
__global__ void k_pool(const int* __restrict__ inputs,
                       const int* __restrict__ as0, const int* __restrict__ as1,
                       const int* __restrict__ ssl0, const int* __restrict__ ssl1,
                       const float* __restrict__ emb){
  int blk = blockIdx.x; int tid = threadIdx.x;
  int node = inputs[blk];
  g_h[blk*DD+tid] = emb[node*DD+tid];
  float p1=0.f, p2=0.f;
  const int* L1[2] = {as0, as1};
  const int* L2[2] = {ssl0, ssl1};
  #pragma unroll
  for(int l=0;l<2;l++){
    float s=0.f,c=0.f;
    #pragma unroll
    for(int n=0;n<NNEI;n++){ int id=L1[l][blk*NNEI+n]; if(id!=0){ s+=emb[id*DD+tid]; c+=1.f; } }
    p1 += s/(c+1e-8f);
    s=0.f;c=0.f;
    #pragma unroll
    for(int n=0;n<NNEI;n++){ int id=L2[l][blk*NNEI+n]; if(id!=0){ s+=emb[id*DD+tid]; c+=1.f; } }
    p2 += s/(c+1e-8f);
  }
  g_hf1[blk*DD+tid] = p1*0.5f;
  g_hf2[blk*DD+tid] = p2*0.5f;
}

// ---------------- k_attr ----------------
__global__ void k_attr(const float* __restrict__ attr_w){
  int blk=blockIdx.x, tid=threadIdx.x;
  __shared__ __align__(16) float hr[DD], fr[DD];
  hr[tid]=g_h[blk*DD+tid]; fr[tid]=g_hf1[blk*DD+tid];
  __syncthreads();
  const float* wt = attr_w + tid;
  float acc=0.f;
  #pragma unroll 8
  for(int k=0;k<DD;k+=4){
    float4 h4=*(const float4*)&hr[k];
    acc=fmaf(h4.x,wt[(k  )*DD],acc); acc=fmaf(h4.y,wt[(k+1)*DD],acc);
    acc=fmaf(h4.z,wt[(k+2)*DD],acc); acc=fmaf(h4.w,wt[(k+3)*DD],acc);
  }
  #pragma unroll 8
  for(int k=0;k<DD;k+=4){
    float4 f4=*(const float4*)&fr[k];
    acc=fmaf(f4.x,wt[(DD+k  )*DD],acc); acc=fmaf(f4.y,wt[(DD+k+1)*DD],acc);
    acc=fmaf(f4.z,wt[(DD+k+2)*DD],acc); acc=fmaf(f4.w,wt[(DD+k+3)*DD],acc);
  }
  float g=sigm(acc);
  float hf = g*hr[tid] + (1.f-g)*fr[tid];
  g_x[blk*DD+tid]=hr[tid];
  g_mirror[blk*DD+tid]=hf;
}

// ---------------- k_sess ----------------
__global__ void k_sess(const int* __restrict__ inputs, const int* __restrict__ item,
                       const float* __restrict__ emb){
  int b=blockIdx.x, tid=threadIdx.x;
  float acc=0.f, cnt=0.f;
  for(int s=0;s<SS;s++){
    int inp=inputs[b*SS+s];
    if(inp!=0){ acc += emb[item[b*SS+s]*DD+tid]; cnt+=1.f; }
  }
  g_sess[b*DD+tid]=acc/cnt;
}

// ---------------- k_att: scalar fused attention (modes 0 & 2; 32 thr, 4 cols/thr) ----------------
__global__ void __launch_bounds__(32) k_att(
                       const int* __restrict__ inputs, const int* __restrict__ adj_all,
                       const float* __restrict__ num, const float* __restrict__ emb,
                       const float* __restrict__ w1, const float* __restrict__ w2,
                       int N, int mode){
  int blk=blockIdx.x; int b=blk/N; int i=blk-b*N; int tid=threadIdx.x;
  int c0=tid, c1=tid+32, c2=tid+64, c3=tid+96;
  __shared__ __align__(16) float nv_s[SAMP][DD];
  __shared__ __align__(16) float sess_s[DD];
  __shared__ float nw_s[SAMP];
  __shared__ int   ci_s[SAMP];

  int node = inputs[b*SS+i];
  if(tid<SAMP){
    ci_s[tid] = adj_all[node*SAMP+tid];
    nw_s[tid] = num[node*SAMP+tid];
  }
  ((float4*)sess_s)[tid] = ((const float4*)&g_sess[b*DD])[tid];
  __syncwarp();
  float4 sv4;
  if(mode==2){
    sv4 = ((const float4*)&g_out0[(b*SS+i)*DD])[tid];
    #pragma unroll
    for(int s=0;s<SAMP;s++)
      ((float4*)nv_s[s])[tid] = ((const float4*)&g_out1[(size_t)(b*600 + i*SAMP+s)*DD])[tid];
  } else {
    sv4 = ((const float4*)&emb[(size_t)node*DD])[tid];
    #pragma unroll
    for(int s=0;s<SAMP;s++)
      ((float4*)nv_s[s])[tid] = ((const float4*)&emb[(size_t)ci_s[s]*DD])[tid];
  }
  ((float4*)&g_cat[(size_t)blk*2*DD])[tid] = sv4;
  __syncwarp();

  float acc0[SAMP], acc1[SAMP], acc2[SAMP], acc3[SAMP];
  {
    float wl0=w1[DD*DD+c0], wl1=w1[DD*DD+c1], wl2=w1[DD*DD+c2], wl3=w1[DD*DD+c3];
    #pragma unroll
    for(int s=0;s<SAMP;s++){
      float nw=nw_s[s];
      acc0[s]=nw*wl0; acc1[s]=nw*wl1; acc2[s]=nw*wl2; acc3[s]=nw*wl3;
    }
  }
  #pragma unroll 1
  for(int d=0;d<DD;d+=4){
    float4 se = *(const float4*)&sess_s[d];
    const float* wr = w1 + d*DD;
    float a00=se.x*wr[c0],      a01=se.x*wr[c1],      a02=se.x*wr[c2],      a03=se.x*wr[c3];
    float a10=se.y*wr[DD+c0],   a11=se.y*wr[DD+c1],   a12=se.y*wr[DD+c2],   a13=se.y*wr[DD+c3];
    float a20=se.z*wr[2*DD+c0], a21=se.z*wr[2*DD+c1], a22=se.z*wr[2*DD+c2], a23=se.z*wr[2*DD+c3];
    float a30=se.w*wr[3*DD+c0], a31=se.w*wr[3*DD+c1], a32=se.w*wr[3*DD+c2], a33=se.w*wr[3*DD+c3];
    #pragma unroll
    for(int s=0;s<SAMP;s++){
      float4 v = *(const float4*)&nv_s[s][d];
      acc0[s] = fmaf(v.x,a00, fmaf(v.y,a10, fmaf(v.z,a20, fmaf(v.w,a30, acc0[s]))));
      acc1[s] = fmaf(v.x,a01, fmaf(v.y,a11, fmaf(v.z,a21, fmaf(v.w,a31, acc1[s]))));
      acc2[s] = fmaf(v.x,a02, fmaf(v.y,a12, fmaf(v.z,a22, fmaf(v.w,a32, acc2[s]))));
      acc3[s] = fmaf(v.x,a03, fmaf(v.y,a13, fmaf(v.z,a23, fmaf(v.w,a33, acc3[s]))));
    }
  }
  float w20=w2[c0], w21=w2[c1], w22=w2[c2], w23=w2[c3];
  float lg[SAMP];
  #pragma unroll
  for(int s=0;s<SAMP;s++){
    float a=acc0[s]; a=(a>0.f)?a:(LEAKC*a);
    float bq=acc1[s]; bq=(bq>0.f)?bq:(LEAKC*bq);
    float cq=acc2[s]; cq=(cq>0.f)?cq:(LEAKC*cq);
    float dq=acc3[s]; dq=(dq>0.f)?dq:(LEAKC*dq);
    float p = a*w20 + bq*w21 + cq*w22 + dq*w23;
    p += __shfl_xor_sync(0xffffffffu, p, 16);
    p += __shfl_xor_sync(0xffffffffu, p, 8);
    p += __shfl_xor_sync(0xffffffffu, p, 4);
    p += __shfl_xor_sync(0xffffffffu, p, 2);
    p += __shfl_xor_sync(0xffffffffu, p, 1);
    lg[s]=p;
  }
  float m=-1e30f;
  #pragma unroll
  for(int s=0;s<SAMP;s++) m=fmaxf(m, lg[s]);
  float alpha[SAMP]; float den=0.f;
  #pragma unroll
  for(int s=0;s<SAMP;s++){ alpha[s]=expf(lg[s]-m); den+=alpha[s]; }
  float inv=1.f/den;
  float g0=0.f,g1=0.f,g2=0.f,g3=0.f;
  #pragma unroll
  for(int s=0;s<SAMP;s++){
    float al=alpha[s];
    g0=fmaf(al,nv_s[s][c0],g0); g1=fmaf(al,nv_s[s][c1],g1);
    g2=fmaf(al,nv_s[s][c2],g2); g3=fmaf(al,nv_s[s][c3],g3);
  }
  float* crow = &g_cat[(size_t)blk*2*DD + DD];
  crow[c0]=g0*inv; crow[c1]=g1*inv; crow[c2]=g2*inv; crow[c3]=g3*inv;
}

// ---------------- k_logits: bf16 TC logits for mode 1 ----------------
// y[r][c] = sum_d (emb[ci(r)][d]*sess[b][d]) * W1[d][c]   (A-scaled trick; B=W1 fixed)
// logit[r] = sum_c leaky(y[r][c] + nw*w1_last[c]) * w2[c]
#define LROWS 128
__global__ void __launch_bounds__(256) k_logits(
    const int* __restrict__ inputs, const int* __restrict__ adj_all,
    const float* __restrict__ num, const float* __restrict__ emb,
    const float* __restrict__ w1last, const float* __restrict__ w2,
    float* __restrict__ logits)
{
  extern __shared__ char smem[];
  const int LDAB = 136;  // bf16 elements per padded row
  __nv_bfloat16* As = (__nv_bfloat16*)smem;                 // [128][136] = 34816 B
  __nv_bfloat16* Bs = (__nv_bfloat16*)(smem + 34816);       // [128][136] = 34816 B
  float* sess_s = (float*)(smem + 69632);
  float* wl_s   = sess_s + DD;
  float* w2_s   = wl_s + DD;
  float* nw_s   = w2_s + DD;
  int*   ci_s   = (int*)(nw_s + LROWS);

  int b = blockIdx.y;
  int row0 = blockIdx.x*LROWS;
  int tid = threadIdx.x, warp = tid>>5, lane = tid&31;

  if(tid<DD){
    sess_s[tid]=g_sess[b*DD+tid];
    wl_s[tid]  =w1last[tid];
    w2_s[tid]  =w2[tid];
  }
  if(tid<LROWS){
    int r = row0 + tid;
    int rr = (r<7200)? r : 7199;
    int gi=rr/SAMP, s=rr-gi*SAMP;
    int pi=gi/SAMP, ps=gi-pi*SAMP;
    int node = adj_all[inputs[b*SS+pi]*SAMP+ps];
    ci_s[tid]=adj_all[node*SAMP+s];
    nw_s[tid]=num[node*SAMP+s];
  }
  // stage B (independent of sess): thread t -> row t/2, 64-col half t%2
  {
    int row=tid>>1, cb=(tid&1)*64;
    const uint4* src=(const uint4*)(g_w1b + row*DD + cb);
    uint4* dst=(uint4*)(Bs + row*LDAB + cb);
    #pragma unroll
    for(int j=0;j<8;j++) dst[j]=src[j];
  }
  __syncthreads();
  // stage A' = emb[ci]*sess, bf16
  {
    int row=tid>>1, cb=(tid&1)*64;
    const float* ap = emb + (size_t)ci_s[row]*DD + cb;
    __nv_bfloat16* dst = As + row*LDAB + cb;
    #pragma unroll
    for(int j=0;j<16;j++){
      float4 v=*(const float4*)&ap[j*4];
      float4 se=*(const float4*)&sess_s[cb+j*4];
      *(__nv_bfloat162*)&dst[j*4]   = __floats2bfloat162_rn(v.x*se.x, v.y*se.y);
      *(__nv_bfloat162*)&dst[j*4+2] = __floats2bfloat162_rn(v.z*se.z, v.w*se.w);
    }
  }
  __syncthreads();

  wmma::fragment<wmma::accumulator,16,16,16,float> acc[8];
  #pragma unroll
  for(int n=0;n<8;n++) wmma::fill_fragment(acc[n], 0.0f);

  #pragma unroll
  for(int k=0;k<DD;k+=16){
    wmma::fragment<wmma::matrix_a,16,16,16,__nv_bfloat16,wmma::row_major> af;
    wmma::load_matrix_sync(af, As + (warp*16)*LDAB + k, LDAB);
    #pragma unroll
    for(int n=0;n<8;n++){
      wmma::fragment<wmma::matrix_b,16,16,16,__nv_bfloat16,wmma::row_major> bf;
      wmma::load_matrix_sync(bf, Bs + k*LDAB + n*16, LDAB);
      wmma::mma_sync(acc[n], af, bf, acc[n]);
    }
  }
  __syncthreads();   // done with Bs; reuse as epilogue buffers

  float* epi = (float*)Bs + warp*320;   // 16x20 floats per warp
  int r2=lane>>1, half=lane&1;
  float nw = nw_s[warp*16+r2];
  float v=0.f;
  #pragma unroll
  for(int n=0;n<8;n++){
    wmma::store_matrix_sync(epi, acc[n], 20, wmma::mem_row_major);
    __syncwarp();
    const float* crow = epi + r2*20 + half*8;
    int cb = n*16 + half*8;
    #pragma unroll
    for(int j=0;j<8;j++){
      float t = crow[j] + nw*wl_s[cb+j];
      t = (t>0.f)?t:(LEAKC*t);
      v = fmaf(t, w2_s[cb+j], v);
    }
    __syncwarp();
  }
  v += __shfl_xor_sync(0xffffffffu, v, 1);
  int rg = row0 + warp*16 + r2;
  if(half==0 && rg<7200) logits[(size_t)b*7200 + rg] = v;
}

// ---------------- k_soft_agg: warp-per-node softmax+agg (mode 1) ----------------
__global__ void __launch_bounds__(256) k_soft_agg(
    const int* __restrict__ inputs, const int* __restrict__ adj_all,
    const float* __restrict__ emb, const float* __restrict__ logits)
{
  int warp = threadIdx.x>>5, lane = threadIdx.x&31;
  int g = blockIdx.x*8 + warp;              // node index in [0, BB*600)
  int b = g/600, i = g - b*600;
  int pi=i/SAMP, ps=i-pi*SAMP;
  int node = adj_all[inputs[b*SS+pi]*SAMP+ps];
  int ci_l=0; float lg_l=0.f;
  if(lane<SAMP){
    ci_l = adj_all[node*SAMP+lane];
    lg_l = logits[(size_t)b*7200 + i*SAMP + lane];
  }
  float lg[SAMP]; int ci[SAMP];
  float m=-1e30f;
  #pragma unroll
  for(int s=0;s<SAMP;s++){
    lg[s]=__shfl_sync(0xffffffffu, lg_l, s);
    ci[s]=__shfl_sync(0xffffffffu, ci_l, s);
    m=fmaxf(m,lg[s]);
  }
  float alpha[SAMP]; float den=0.f;
  #pragma unroll
  for(int s=0;s<SAMP;s++){ alpha[s]=expf(lg[s]-m); den+=alpha[s]; }
  float inv=1.f/den;
  float4 sv4 = ((const float4*)&emb[(size_t)node*DD])[lane];
  float a0=0.f,a1=0.f,a2=0.f,a3=0.f;
  #pragma unroll
  for(int s=0;s<SAMP;s++){
    float4 nv4 = ((const float4*)&emb[(size_t)ci[s]*DD])[lane];
    float al = alpha[s];
    a0=fmaf(al,nv4.x,a0); a1=fmaf(al,nv4.y,a1); a2=fmaf(al,nv4.z,a2); a3=fmaf(al,nv4.w,a3);
  }
  float* crow = &g_cat[(size_t)g*2*DD];
  ((float4*)crow)[lane] = sv4;
  float4 ag; ag.x=a0*inv; ag.y=a1*inv; ag.z=a2*inv; ag.w=a3*inv;
  ((float4*)(crow+DD))[lane] = ag;
}

// ---------------- k_gemm3: out = tanh(cat @ W3), tiled 32 rows x 128 cols ----------------
__global__ void __launch_bounds__(128) k_gemm3(const float* __restrict__ w3,
                                               float* __restrict__ out){
  int row0 = blockIdx.x*32; int tid=threadIdx.x;
  int c = tid;
  __shared__ __align__(16) float As[16][32];
  float acc[32];
  #pragma unroll
  for(int r=0;r<32;r++) acc[r]=0.f;
  int rld = tid & 31;
  int kq  = tid >> 5;
  for(int k0=0;k0<2*DD;k0+=16){
    float4 av = *(const float4*)&g_cat[(size_t)(row0+rld)*2*DD + k0 + kq*4];
    As[kq*4+0][rld]=av.x; As[kq*4+1][rld]=av.y; As[kq*4+2][rld]=av.z; As[kq*4+3][rld]=av.w;
    __syncthreads();
    const float* w3c = w3 + (size_t)k0*DD + c;
    #pragma unroll 4
    for(int k=0;k<16;k++){
      float bk = w3c[k*DD];
      #pragma unroll
      for(int r4=0;r4<8;r4++){
        float4 a = *(const float4*)&As[k][r4*4];
        acc[r4*4+0]=fmaf(a.x,bk,acc[r4*4+0]);
        acc[r4*4+1]=fmaf(a.y,bk,acc[r4*4+1]);
        acc[r4*4+2]=fmaf(a.z,bk,acc[r4*4+2]);
        acc[r4*4+3]=fmaf(a.w,bk,acc[r4*4+3]);
      }
    }
    __syncthreads();
  }
  #pragma unroll
  for(int r=0;r<32;r++)
    out[(size_t)(row0+r)*DD + c] = tanhf(acc[r]);
}

// ---------------- k_attx ----------------
__global__ void k_attx(const int* __restrict__ adj, const float* __restrict__ a_local){
  int b=blockIdx.x; int tid=threadIdx.x;  // 256 threads
  __shared__ __align__(16) float xs[SS][DD+4];
  __shared__ __align__(16) float al_s[4][DD];
  __shared__ float att[SS][SS+2];
  for(int idx=tid; idx<SS*DD; idx+=256){
    int i=idx>>7, d=idx&127;
    xs[i][d]=g_x[(b*SS+i)*DD+d];
  }
  for(int idx=tid; idx<4*DD; idx+=256)
    al_s[idx>>7][idx&127]=a_local[idx];
  __syncthreads();
  for(int p=tid;p<SS*SS;p+=256){
    int i=p/SS, j=p-i*SS;
    int k=adj[b*SS*SS+p];
    float e=-9e15f;
    if(k>=1 && k<=4){
      const float* al = al_s[k-1];
      float ds=0.f;
      #pragma unroll 8
      for(int d=0;d<DD;d+=4){
        float4 xi=*(const float4*)&xs[i][d];
        float4 xj=*(const float4*)&xs[j][d];
        float4 av=*(const float4*)&al[d];
        ds += xi.x*xj.x*av.x + xi.y*xj.y*av.y + xi.z*xj.z*av.z + xi.w*xj.w*av.w;
      }
      e = (ds>0.f)?ds:(LEAKC*ds);
    }
    att[i][j]=e;
  }
  __syncthreads();
  if(tid<SS){
    float m=-1e30f;
    for(int j=0;j<SS;j++) m=fmaxf(m,att[tid][j]);
    float den=0.f;
    for(int j=0;j<SS;j++){ float e=expf(att[tid][j]-m); att[tid][j]=e; den+=e; }
    float inv=1.f/den;
    for(int j=0;j<SS;j++) att[tid][j]*=inv;
  }
  __syncthreads();
  for(int q=tid;q<SS*DD;q+=256){
    int i=q>>7, d=q&127;
    float acc=0.f;
    for(int j=0;j<SS;j++) acc += att[i][j]*xs[j][d];
    g_xnew[(b*SS+i)*DD+d]=acc;
  }
}

// ---------------- k_gate ----------------
__global__ void k_gate(const float* __restrict__ w1, const float* __restrict__ w2){
  int blk=blockIdx.x, tid=threadIdx.x;
  __shared__ __align__(16) float xn[DD], mr[DD];
  xn[tid]=g_xnew[blk*DD+tid]; mr[tid]=g_mirror[blk*DD+tid];
  __syncthreads();
  const float* w1t=w1+tid; const float* w2t=w2+tid;
  float acc=0.f;
  #pragma unroll 8
  for(int k=0;k<DD;k+=4){
    float4 x4=*(const float4*)&xn[k];
    float4 m4=*(const float4*)&mr[k];
    acc=fmaf(x4.x,w1t[(k  )*DD],acc); acc=fmaf(m4.x,w2t[(k  )*DD],acc);
    acc=fmaf(x4.y,w1t[(k+1)*DD],acc); acc=fmaf(m4.y,w2t[(k+1)*DD],acc);
    acc=fmaf(x4.z,w1t[(k+2)*DD],acc); acc=fmaf(m4.z,w2t[(k+2)*DD],acc);
    acc=fmaf(x4.w,w1t[(k+3)*DD],acc); acc=fmaf(m4.w,w2t[(k+3)*DD],acc);
  }
  float gm=sigm(acc);
  float xv=xn[tid], mv=mr[tid];
  g_x[blk*DD+tid]     = gm*xv + (1.f-gm)*mv;
  g_mirror[blk*DD+tid]= gm*mv + (1.f-gm)*xv;
}

// ---------------- k_highway ----------------
__global__ void k_highway(const float* __restrict__ hw){
  int blk=blockIdx.x, tid=threadIdx.x;
  __shared__ __align__(16) float hr[DD], xr[DD];
  hr[tid]=g_h[blk*DD+tid]; xr[tid]=g_x[blk*DD+tid];
  __syncthreads();
  const float* wt=hw+tid;
  float acc=0.f;
  #pragma unroll 8
  for(int k=0;k<DD;k+=4){
    float4 h4=*(const float4*)&hr[k];
    float4 x4=*(const float4*)&xr[k];
    acc=fmaf(h4.x,wt[(k  )*DD],acc); acc=fmaf(x4.x,wt[(DD+k  )*DD],acc);
    acc=fmaf(h4.y,wt[(k+1)*DD],acc); acc=fmaf(x4.y,wt[(DD+k+1)*DD],acc);
    acc=fmaf(h4.z,wt[(k+2)*DD],acc); acc=fmaf(x4.z,wt[(DD+k+2)*DD],acc);
    acc=fmaf(h4.w,wt[(k+3)*DD],acc); acc=fmaf(x4.w,wt[(DD+k+3)*DD],acc);
  }
  float g=sigm(acc);
  float xd=g*hr[tid]+(1.f-g)*xr[tid];
  g_xdot[blk*DD+tid]=xd;
  int s=blk%SS;
  if(s==SS-1) g_hlocal[(blk/SS)*DD+tid]=xd;
}

// ---------------- k_hs ----------------
__global__ void k_hs(const int* __restrict__ inputs){
  int b=blockIdx.x, tid=threadIdx.x;
  float acc=0.f, cnt=0.f;
  for(int s=0;s<SS;s++){
    if(inputs[b*SS+s]!=0){ acc += g_hglob[(b*SS+s)*DD+tid]; cnt+=1.f; }
  }
  g_hs[b*DD+tid]=acc/cnt;
}

// ---------------- k_c2 ----------------
__global__ void k_c2(const float* __restrict__ glu2, const float* __restrict__ glu4,
                     const float* __restrict__ glu4b){
  int b=blockIdx.x, tid=threadIdx.x;
  __shared__ __align__(16) float hsr[DD], hlr[DD];
  hsr[tid]=g_hs[b*DD+tid]; hlr[tid]=g_hlocal[b*DD+tid];
  __syncthreads();
  float acc=glu4b[tid];
  const float* w2t=glu2+tid; const float* w4t=glu4+tid;
  #pragma unroll 8
  for(int k=0;k<DD;k+=4){
    float4 s4=*(const float4*)&hsr[k];
    float4 l4=*(const float4*)&hlr[k];
    acc=fmaf(s4.x,w2t[(k  )*DD],acc); acc=fmaf(l4.x,w4t[(k  )*DD],acc);
    acc=fmaf(s4.y,w2t[(k+1)*DD],acc); acc=fmaf(l4.y,w4t[(k+1)*DD],acc);
    acc=fmaf(s4.z,w2t[(k+2)*DD],acc); acc=fmaf(l4.z,w4t[(k+2)*DD],acc);
    acc=fmaf(s4.w,w2t[(k+3)*DD],acc); acc=fmaf(l4.w,w4t[(k+3)*DD],acc);
  }
  g_c2[b*DD+tid]=acc;
}

// ---------------- k_beta ----------------
__global__ void k_beta(const int* __restrict__ inputs, const float* __restrict__ pos,
                       const float* __restrict__ glu1, const float* __restrict__ ws){
  int blk=blockIdx.x, tid=threadIdx.x;
  int s=blk%SS, b=blk/SS;
  __shared__ __align__(16) float hp[DD];
  __shared__ float red[DD];
  hp[tid]=g_xdot[blk*DD+tid] + pos[s*DD+tid];
  __syncthreads();
  const float* wt=glu1+tid;
  float acc=0.f;
  #pragma unroll 8
  for(int k=0;k<DD;k+=4){
    float4 h4=*(const float4*)&hp[k];
    acc=fmaf(h4.x,wt[(k  )*DD],acc); acc=fmaf(h4.y,wt[(k+1)*DD],acc);
    acc=fmaf(h4.z,wt[(k+2)*DD],acc); acc=fmaf(h4.w,wt[(k+3)*DD],acc);
  }
  float nh=sigm(acc + g_c2[b*DD+tid]);
  red[tid]=nh*ws[tid];
  __syncthreads();
  for(int off=64;off>0;off>>=1){ if(tid<off) red[tid]+=red[tid+off]; __syncthreads(); }
  if(tid==0){
    float mi=(inputs[blk]!=0)?1.f:0.f;
    g_beta[blk]=red[0]*mi;
  }
}

// ---------------- k_zg ----------------
__global__ void k_zg(const float* __restrict__ pos){
  int b=blockIdx.x, tid=threadIdx.x;
  float acc=0.f;
  for(int s=0;s<SS;s++)
    acc += g_beta[b*SS+s]*(g_xdot[(b*SS+s)*DD+tid]+pos[s*DD+tid]);
  g_zg[b*DD+tid]=acc;
}

// ---------------- k_zh ----------------
__global__ void k_zh(const float* __restrict__ gatew){
  int b=blockIdx.x, tid=threadIdx.x;
  __shared__ __align__(16) float zgr[DD], hlr[DD];
  zgr[tid]=g_zg[b*DD+tid]; hlr[tid]=g_hlocal[b*DD+tid];
  __syncthreads();
  const float* wt=gatew+tid;
  float acc=0.f;
  #pragma unroll 8
  for(int k=0;k<DD;k+=4){
    float4 z4=*(const float4*)&zgr[k];
    float4 l4=*(const float4*)&hlr[k];
    acc=fmaf(z4.x,wt[(k  )*DD],acc); acc=fmaf(l4.x,wt[(DD+k  )*DD],acc);
    acc=fmaf(z4.y,wt[(k+1)*DD],acc); acc=fmaf(l4.y,wt[(DD+k+1)*DD],acc);
    acc=fmaf(z4.z,wt[(k+2)*DD],acc); acc=fmaf(l4.z,wt[(DD+k+2)*DD],acc);
    acc=fmaf(z4.w,wt[(k+3)*DD],acc); acc=fmaf(l4.w,wt[(DD+k+3)*DD],acc);
  }
  float gf=sigm(acc)*0.1f;
  float zh=gf*hlr[tid]+(1.f-gf)*zgr[tid];
  g_zhT[tid*BB+b]=zh;
}

// ---------------- k_scores ----------------
__global__ void k_scores(const float* __restrict__ emb, float* __restrict__ out){
  int n0 = blockIdx.x*32; int tid=threadIdx.x;
  __shared__ __align__(16) float es[32][DD];
  int nmax = NSCORE - n0; if(nmax>32) nmax=32;
  for(int idx=tid; idx<nmax*DD; idx+=128){
    int nn=idx>>7, d=idx&127;
    es[nn][d]=emb[(size_t)(n0+nn+1)*DD+d];
  }
  __syncthreads();
  float accv[32];
  #pragma unroll
  for(int nn=0;nn<32;nn++) accv[nn]=0.f;
  for(int d=0;d<DD;d+=4){
    float z0=g_zhT[(d  )*BB+tid];
    float z1=g_zhT[(d+1)*BB+tid];
    float z2=g_zhT[(d+2)*BB+tid];
    float z3=g_zhT[(d+3)*BB+tid];
    #pragma unroll
    for(int nn=0;nn<32;nn++){
      float4 e=*reinterpret_cast<const float4*>(&es[nn][d]);
      accv[nn]=fmaf(z0,e.x,fmaf(z1,e.y,fmaf(z2,e.z,fmaf(z3,e.w,accv[nn]))));
    }
  }
  for(int nn=0;nn<nmax;nn++)
    out[1 + (size_t)tid*NSCORE + n0+nn] = accv[nn];
}

// ---------------- k_simi ----------------
__global__ void k_simi(const int* __restrict__ simi_mask){
  int blk=blockIdx.x; int b=blk/SS; int tid=threadIdx.x; // 64 threads
  __shared__ float f1[DD];
  __shared__ float sims[SS];
  f1[tid]   =g_hf1[blk*DD+tid];
  f1[tid+64]=g_hf1[blk*DD+tid+64];
  __syncthreads();
  if(tid<SS){
    const float* f2=&g_hf2[(b*SS+tid)*DD];
    float acc=0.f;
    for(int d=0;d<DD;d++) acc+=f1[d]*f2[d];
    sims[tid]=acc*2.0f;   // 1/TEMP
  }
  __syncthreads();
  if(tid==0){
    float m=-1e30f;
    for(int j=0;j<SS;j++) m=fmaxf(m,sims[j]);
    float den=0.f;
    for(int j=0;j<SS;j++) den+=expf(sims[j]-m);
    float loss=0.f;
    for(int j=0;j<SS;j++){
      float p=expf(sims[j]-m)/den;
      float l=-logf(p+1e-8f);
      if(simi_mask[blk*SS+j]==1) loss+=l;
    }
    g_partial[blk]=loss;
  }
}

__global__ void k_simi_final(float* __restrict__ out){
  int tid=threadIdx.x; // 128
  __shared__ float red[128];
  float a=0.f;
  for(int i=tid;i<BB*SS;i+=128) a+=g_partial[i];
  red[tid]=a; __syncthreads();
  for(int off=64;off>0;off>>=1){ if(tid<off) red[tid]+=red[tid+off]; __syncthreads(); }
  if(tid==0) out[0]=red[0]/(float)BB;
}

// ---------------- launch ----------------
extern "C" void kernel_launch(void* const* d_in, const int* in_sizes, int n_in,
                              void* d_out, int out_size){
  const int*   inputs =(const int*)  d_in[0];
  const int*   adj    =(const int*)  d_in[1];
  const int*   item   =(const int*)  d_in[2];
  const int*   simi   =(const int*)  d_in[3];
  const int*   as0    =(const int*)  d_in[4];
  const int*   as1    =(const int*)  d_in[5];
  const int*   ssl0   =(const int*)  d_in[6];
  const int*   ssl1   =(const int*)  d_in[7];
  // d_in[8] = last_item_mask (statically [:, -1]; unused)
  const int*   adj_all=(const int*)  d_in[9];
  const float* num    =(const float*)d_in[10];
  const float* emb    =(const float*)d_in[11];
  const float* pos    =(const float*)d_in[12];
  const float* a_local=(const float*)d_in[13];
  const float* mir1   =(const float*)d_in[14];
  const float* mir2   =(const float*)d_in[15];
  const float* gw1    =(const float*)d_in[16];
  const float* gw2    =(const float*)d_in[17];
  const float* gw3    =(const float*)d_in[18];
  const float* attr   =(const float*)d_in[19];
  const float* hww    =(const float*)d_in[20];
  const float* glu1   =(const float*)d_in[21];
  const float* glu2   =(const float*)d_in[22];
  const float* glu4   =(const float*)d_in[23];
  const float* glu4b  =(const float*)d_in[24];
  const float* ws     =(const float*)d_in[25];
  const float* gatew  =(const float*)d_in[26];
  float* out=(float*)d_out;

  float* p_out0;   cudaGetSymbolAddress((void**)&p_out0,  g_out0);
  float* p_out1;   cudaGetSymbolAddress((void**)&p_out1,  g_out1);
  float* p_hglob;  cudaGetSymbolAddress((void**)&p_hglob, g_hglob);
  float* p_logits; cudaGetSymbolAddress((void**)&p_logits,g_logits);

  const int LOGITS_SMEM = 34816*2 + 3*DD*4 + LROWS*4 + LROWS*4;  // 72192 B
  cudaFuncSetAttribute(k_logits, cudaFuncAttributeMaxDynamicSharedMemorySize, LOGITS_SMEM);
  cudaFuncSetAttribute(k_logits, cudaFuncAttributePreferredSharedMemoryCarveout, 100);

  k_w1bf<<<DD*DD/256,256>>>(gw1);                                 // 1
  k_pool<<<BB*SS,DD>>>(inputs, as0, as1, ssl0, ssl1, emb);        // 2
  k_attr<<<BB*SS,DD>>>(attr);                                     // 3
  k_sess<<<BB,DD>>>(inputs,item,emb);                             // 4

  // mode 1 FIRST (independent of mode 0) — ncu -s 5 lands on k_logits
  {
    dim3 g((7200+LROWS-1)/LROWS, BB);   // 57 x 128
    k_logits<<<g,256,LOGITS_SMEM>>>(inputs,adj_all,num, emb, gw1+DD*DD, gw2, p_logits);  // 5
  }
  k_soft_agg<<<BB*600/8,256>>>(inputs,adj_all, emb, p_logits);
  k_gemm3<<<BB*600/32,128>>>(gw3, p_out1);

  // mode 0: scalar fused path (hop-0 weights)
  k_att<<<BB*SS,32>>>(inputs,adj_all,num, emb, gw1, gw2, SS, 0);
  k_gemm3<<<BB*SS/32,128>>>(gw3, p_out0);

  // mode 2: scalar fused path (hop-1 weights)
  k_att<<<BB*SS,32>>>(inputs,adj_all,num, emb, gw1+129*DD, gw2+DD, SS, 2);
  k_gemm3<<<BB*SS/32,128>>>(gw3+256*DD, p_hglob);

  // local branch: 2 iterations
  for(int it=0; it<2; it++){
    k_attx<<<BB,256>>>(adj, a_local + it*4*DD);
    k_gate<<<BB*SS,DD>>>(mir1 + it*DD*DD, mir2 + it*DD*DD);
  }
  k_highway<<<BB*SS,DD>>>(hww);
  k_hs<<<BB,DD>>>(inputs);
  k_c2<<<BB,DD>>>(glu2,glu4,glu4b);
  k_beta<<<BB*SS,DD>>>(inputs,pos,glu1,ws);
  k_zg<<<BB,DD>>>(pos);
  k_zh<<<BB,DD>>>(gatew);

  k_scores<<<(NSCORE+31)/32,128>>>(emb,out);
  k_simi<<<BB*SS,64>>>(simi);
  k_simi_final<<<1,128>>>(out);
}

// round 10
// speedup vs baseline: 1.1558x; 1.1558x over previous
#include <cuda_runtime.h>
#include <cuda_bf16.h>
#include <math.h>
#include <mma.h>
using namespace nvcuda;

#define BB 128
#define SS 50
#define DD 128
#define NNODE 40000
#define SAMP 12
#define NNEI 8
#define LEAKC 0.2f
#define NSCORE 39999

// ---------------- scratch (device globals; no allocation) ----------------
__device__ float g_h[BB*SS*DD];
__device__ float g_hf1[BB*SS*DD];
__device__ float g_hf2[BB*SS*DD];
__device__ float g_x[BB*SS*DD];
__device__ float g_mirror[BB*SS*DD];
__device__ float g_xnew[BB*SS*DD];
__device__ float g_xdot[BB*SS*DD];
__device__ float g_sess[BB*DD];
__device__ float g_out0[BB*SS*DD];
__device__ float g_out1[BB*600*DD];
__device__ float g_hglob[BB*SS*DD];
__device__ float g_hs[BB*DD];
__device__ float g_hlocal[BB*DD];
__device__ float g_c2[BB*DD];
__device__ float g_beta[BB*SS];
__device__ float g_zg[BB*DD];
__device__ float g_zhT[DD*BB];
__device__ float g_partial[BB*SS];
__device__ float g_cat[BB*SS*2*DD];     // [rows][256] concat buffer (modes 0/2 only now)
__device__ float g_logits[BB*7200];     // per-sample attention logits (mode 1)
__device__ __nv_bfloat16 g_w1b[DD*DD];  // W1 (first 128 rows) in bf16
__device__ float g_E3top[NNODE*DD];     // emb @ W3[0:128]
__device__ float g_E3bot[NNODE*DD];     // emb @ W3[128:256]

__device__ __forceinline__ float sigm(float x){ return 1.0f/(1.0f+expf(-x)); }

// ---------------- k_w1bf: convert W1[0:128][:] to bf16 ----------------
__global__ void k_w1bf(const float* __restrict__ w1){
  int i = blockIdx.x*256 + threadIdx.x;
  g_w1b[i] = __float2bfloat16(w1[i]);
}

// ---------------- k_e3: E3top/E3bot = emb @ W3top / W3bot (fp32 exact) ----------------
__global__ void __launch_bounds__(128) k_e3(const float* __restrict__ emb,
                                            const float* __restrict__ w3){
  int row0 = blockIdx.x*32; int c = threadIdx.x;
  __shared__ __align__(16) float As[16][32];
  float accT[32], accB[32];
  #pragma unroll
  for(int r=0;r<32;r++){ accT[r]=0.f; accB[r]=0.f; }
  int rld = c & 31;
  int kq  = c >> 5;
  for(int k0=0;k0<DD;k0+=16){
    float4 av = *(const float4*)&emb[(size_t)(row0+rld)*DD + k0 + kq*4];
    As[kq*4+0][rld]=av.x; As[kq*4+1][rld]=av.y; As[kq*4+2][rld]=av.z; As[kq*4+3][rld]=av.w;
    __syncthreads();
    const float* wT = w3 + (size_t)k0*DD + c;
    const float* wB = w3 + (size_t)(k0+DD)*DD + c;
    #pragma unroll 4
    for(int k=0;k<16;k++){
      float bT = wT[k*DD];
      float bB = wB[k*DD];
      #pragma unroll
      for(int r4=0;r4<8;r4++){
        float4 a = *(const float4*)&As[k][r4*4];
        accT[r4*4+0]=fmaf(a.x,bT,accT[r4*4+0]); accB[r4*4+0]=fmaf(a.x,bB,accB[r4*4+0]);
        accT[r4*4+1]=fmaf(a.y,bT,accT[r4*4+1]); accB[r4*4+1]=fmaf(a.y,bB,accB[r4*4+1]);
        accT[r4*4+2]=fmaf(a.z,bT,accT[r4*4+2]); accB[r4*4+2]=fmaf(a.z,bB,accB[r4*4+2]);
        accT[r4*4+3]=fmaf(a.w,bT,accT[r4*4+3]); accB[r4*4+3]=fmaf(a.w,bB,accB[r4*4+3]);
      }
    }
    __syncthreads();
  }
  #pragma unroll
  for(int r=0;r<32;r++){
    g_E3top[(size_t)(row0+r)*DD + c] = accT[r];
    g_E3bot[(size_t)(row0+r)*DD + c] = accB[r];
  }
}

// ---------------- k_pool: h, hf1, hf2 ----------------
__global__ void k_pool(const int* __restrict__ inputs,
                       const int* __restrict__ as0, const int* __restrict__ as1,
                       const int* __restrict__ ssl0, const int* __restrict__ ssl1,
                       const float* __restrict__ emb){
  int blk = blockIdx.x; int tid = threadIdx.x;
  int node = inputs[blk];
  g_h[blk*DD+tid] = emb[node*DD+tid];
  float p1=0.f, p2=0.f;
  const int* L1[2] = {as0, as1};
  const int* L2[2] = {ssl0, ssl1};
  #pragma unroll
  for(int l=0;l<2;l++){
    float s=0.f,c=0.f;
    #pragma unroll
    for(int n=0;n<NNEI;n++){ int id=L1[l][blk*NNEI+n]; if(id!=0){ s+=emb[id*DD+tid]; c+=1.f; } }
    p1 += s/(c+1e-8f);
    s=0.f;c=0.f;
    #pragma unroll
    for(int n=0;n<NNEI;n++){ int id=L2[l][blk*NNEI+n]; if(id!=0){ s+=emb[id*DD+tid]; c+=1.f; } }
    p2 += s/(c+1e-8f);
  }
  g_hf1[blk*DD+tid] = p1*0.5f;
  g_hf2[blk*DD+tid] = p2*0.5f;
}

// ---------------- k_attr ----------------
__global__ void k_attr(const float* __restrict__ attr_w){
  int blk=blockIdx.x, tid=threadIdx.x;
  __shared__ __align__(16) float hr[DD], fr[DD];
  hr[tid]=g_h[blk*DD+tid]; fr[tid]=g_hf1[blk*DD+tid];
  __syncthreads();
  const float* wt = attr_w + tid;
  float acc=0.f;
  #pragma unroll 8
  for(int k=0;k<DD;k+=4){
    float4 h4=*(const float4*)&hr[k];
    acc=fmaf(h4.x,wt[(k  )*DD],acc); acc=fmaf(h4.y,wt[(k+1)*DD],acc);
    acc=fmaf(h4.z,wt[(k+2)*DD],acc); acc=fmaf(h4.w,wt[(k+3)*DD],acc);
  }
  #pragma unroll 8
  for(int k=0;k<DD;k+=4){
    float4 f4=*(const float4*)&fr[k];
    acc=fmaf(f4.x,wt[(DD+k  )*DD],acc); acc=fmaf(f4.y,wt[(DD+k+1)*DD],acc);
    acc=fmaf(f4.z,wt[(DD+k+2)*DD],acc); acc=fmaf(f4.w,wt[(DD+k+3)*DD],acc);
  }
  float g=sigm(acc);
  float hf = g*hr[tid] + (1.f-g)*fr[tid];
  g_x[blk*DD+tid]=hr[tid];
  g_mirror[blk*DD+tid]=hf;
}

// ---------------- k_sess ----------------
__global__ void k_sess(const int* __restrict__ inputs, const int* __restrict__ item,
                       const float* __restrict__ emb){
  int b=blockIdx.x, tid=threadIdx.x;
  float acc=0.f, cnt=0.f;
  for(int s=0;s<SS;s++){
    int inp=inputs[b*SS+s];
    if(inp!=0){ acc += emb[item[b*SS+s]*DD+tid]; cnt+=1.f; }
  }
  g_sess[b*DD+tid]=acc/cnt;
}

// ---------------- k_att: scalar fused attention (modes 0 & 2; 32 thr, 4 cols/thr) ----------------
__global__ void __launch_bounds__(32) k_att(
                       const int* __restrict__ inputs, const int* __restrict__ adj_all,
                       const float* __restrict__ num, const float* __restrict__ emb,
                       const float* __restrict__ w1, const float* __restrict__ w2,
                       int N, int mode){
  int blk=blockIdx.x; int b=blk/N; int i=blk-b*N; int tid=threadIdx.x;
  int c0=tid, c1=tid+32, c2=tid+64, c3=tid+96;
  __shared__ __align__(16) float nv_s[SAMP][DD];
  __shared__ __align__(16) float sess_s[DD];
  __shared__ float nw_s[SAMP];
  __shared__ int   ci_s[SAMP];

  int node = inputs[b*SS+i];
  if(tid<SAMP){
    ci_s[tid] = adj_all[node*SAMP+tid];
    nw_s[tid] = num[node*SAMP+tid];
  }
  ((float4*)sess_s)[tid] = ((const float4*)&g_sess[b*DD])[tid];
  __syncwarp();
  float4 sv4;
  if(mode==2){
    sv4 = ((const float4*)&g_out0[(b*SS+i)*DD])[tid];
    #pragma unroll
    for(int s=0;s<SAMP;s++)
      ((float4*)nv_s[s])[tid] = ((const float4*)&g_out1[(size_t)(b*600 + i*SAMP+s)*DD])[tid];
  } else {
    sv4 = ((const float4*)&emb[(size_t)node*DD])[tid];
    #pragma unroll
    for(int s=0;s<SAMP;s++)
      ((float4*)nv_s[s])[tid] = ((const float4*)&emb[(size_t)ci_s[s]*DD])[tid];
  }
  ((float4*)&g_cat[(size_t)blk*2*DD])[tid] = sv4;
  __syncwarp();

  float acc0[SAMP], acc1[SAMP], acc2[SAMP], acc3[SAMP];
  {
    float wl0=w1[DD*DD+c0], wl1=w1[DD*DD+c1], wl2=w1[DD*DD+c2], wl3=w1[DD*DD+c3];
    #pragma unroll
    for(int s=0;s<SAMP;s++){
      float nw=nw_s[s];
      acc0[s]=nw*wl0; acc1[s]=nw*wl1; acc2[s]=nw*wl2; acc3[s]=nw*wl3;
    }
  }
  #pragma unroll 1
  for(int d=0;d<DD;d+=4){
    float4 se = *(const float4*)&sess_s[d];
    const float* wr = w1 + d*DD;
    float a00=se.x*wr[c0],      a01=se.x*wr[c1],      a02=se.x*wr[c2],      a03=se.x*wr[c3];
    float a10=se.y*wr[DD+c0],   a11=se.y*wr[DD+c1],   a12=se.y*wr[DD+c2],   a13=se.y*wr[DD+c3];
    float a20=se.z*wr[2*DD+c0], a21=se.z*wr[2*DD+c1], a22=se.z*wr[2*DD+c2], a23=se.z*wr[2*DD+c3];
    float a30=se.w*wr[3*DD+c0], a31=se.w*wr[3*DD+c1], a32=se.w*wr[3*DD+c2], a33=se.w*wr[3*DD+c3];
    #pragma unroll
    for(int s=0;s<SAMP;s++){
      float4 v = *(const float4*)&nv_s[s][d];
      acc0[s] = fmaf(v.x,a00, fmaf(v.y,a10, fmaf(v.z,a20, fmaf(v.w,a30, acc0[s]))));
      acc1[s] = fmaf(v.x,a01, fmaf(v.y,a11, fmaf(v.z,a21, fmaf(v.w,a31, acc1[s]))));
      acc2[s] = fmaf(v.x,a02, fmaf(v.y,a12, fmaf(v.z,a22, fmaf(v.w,a32, acc2[s]))));
      acc3[s] = fmaf(v.x,a03, fmaf(v.y,a13, fmaf(v.z,a23, fmaf(v.w,a33, acc3[s]))));
    }
  }
  float w20=w2[c0], w21=w2[c1], w22=w2[c2], w23=w2[c3];
  float lg[SAMP];
  #pragma unroll
  for(int s=0;s<SAMP;s++){
    float a=acc0[s]; a=(a>0.f)?a:(LEAKC*a);
    float bq=acc1[s]; bq=(bq>0.f)?bq:(LEAKC*bq);
    float cq=acc2[s]; cq=(cq>0.f)?cq:(LEAKC*cq);
    float dq=acc3[s]; dq=(dq>0.f)?dq:(LEAKC*dq);
    float p = a*w20 + bq*w21 + cq*w22 + dq*w23;
    p += __shfl_xor_sync(0xffffffffu, p, 16);
    p += __shfl_xor_sync(0xffffffffu, p, 8);
    p += __shfl_xor_sync(0xffffffffu, p, 4);
    p += __shfl_xor_sync(0xffffffffu, p, 2);
    p += __shfl_xor_sync(0xffffffffu, p, 1);
    lg[s]=p;
  }
  float m=-1e30f;
  #pragma unroll
  for(int s=0;s<SAMP;s++) m=fmaxf(m, lg[s]);
  float alpha[SAMP]; float den=0.f;
  #pragma unroll
  for(int s=0;s<SAMP;s++){ alpha[s]=expf(lg[s]-m); den+=alpha[s]; }
  float inv=1.f/den;
  float g0=0.f,g1=0.f,g2=0.f,g3=0.f;
  #pragma unroll
  for(int s=0;s<SAMP;s++){
    float al=alpha[s];
    g0=fmaf(al,nv_s[s][c0],g0); g1=fmaf(al,nv_s[s][c1],g1);
    g2=fmaf(al,nv_s[s][c2],g2); g3=fmaf(al,nv_s[s][c3],g3);
  }
  float* crow = &g_cat[(size_t)blk*2*DD + DD];
  crow[c0]=g0*inv; crow[c1]=g1*inv; crow[c2]=g2*inv; crow[c3]=g3*inv;
}

// ---------------- k_logits: bf16 TC logits for mode 1 (256 rows/CTA, 512 thr) ----------------
// y[r][c] = sum_d (emb[ci(r)][d]*sess[b][d]) * W1[d][c]   (A-scaled; B=W1 fixed)
// logit[r] = sum_c leaky(y[r][c] + nw*w1_last[c]) * w2[c]
#define LROWS 256
__global__ void __launch_bounds__(512) k_logits(
    const int* __restrict__ inputs, const int* __restrict__ adj_all,
    const float* __restrict__ num, const float* __restrict__ emb,
    const float* __restrict__ w1last, const float* __restrict__ w2,
    float* __restrict__ logits)
{
  extern __shared__ char smem[];
  const int LDAB = 136;  // bf16 elements per padded row
  __nv_bfloat16* As = (__nv_bfloat16*)smem;                 // [256][136] = 69632 B
  __nv_bfloat16* Bs = (__nv_bfloat16*)(smem + 69632);       // [128][136] = 34816 B
  float* sess_s = (float*)(smem + 104448);
  float* wl_s   = sess_s + DD;
  float* w2_s   = wl_s + DD;
  float* nw_s   = w2_s + DD;
  int*   ci_s   = (int*)(nw_s + LROWS);

  int b = blockIdx.y;
  int row0 = blockIdx.x*LROWS;
  int tid = threadIdx.x, warp = tid>>5, lane = tid&31;

  if(tid<DD){
    sess_s[tid]=g_sess[b*DD+tid];
    wl_s[tid]  =w1last[tid];
    w2_s[tid]  =w2[tid];
  }
  if(tid<LROWS){
    int r = row0 + tid;
    int rr = (r<7200)? r : 7199;
    int gi=rr/SAMP, s=rr-gi*SAMP;
    int pi=gi/SAMP, ps=gi-pi*SAMP;
    int node = adj_all[inputs[b*SS+pi]*SAMP+ps];
    ci_s[tid]=adj_all[node*SAMP+s];
    nw_s[tid]=num[node*SAMP+s];
  }
  // stage B: 512 thr -> row=tid/4, 32-col quarter
  {
    int row=tid>>2, qb=(tid&3)*32;
    const uint4* src=(const uint4*)(g_w1b + row*DD + qb);
    uint4* dst=(uint4*)(Bs + row*LDAB + qb);
    #pragma unroll
    for(int j=0;j<4;j++) dst[j]=src[j];
  }
  __syncthreads();
  // stage A' = emb[ci]*sess, bf16 (2 thr/row, 64 cols each)
  {
    int row=tid>>1, cb=(tid&1)*64;
    const float* ap = emb + (size_t)ci_s[row]*DD + cb;
    __nv_bfloat16* dst = As + row*LDAB + cb;
    #pragma unroll
    for(int j=0;j<16;j++){
      float4 v=*(const float4*)&ap[j*4];
      float4 se=*(const float4*)&sess_s[cb+j*4];
      *(__nv_bfloat162*)&dst[j*4]   = __floats2bfloat162_rn(v.x*se.x, v.y*se.y);
      *(__nv_bfloat162*)&dst[j*4+2] = __floats2bfloat162_rn(v.z*se.z, v.w*se.w);
    }
  }
  __syncthreads();

  wmma::fragment<wmma::accumulator,16,16,16,float> acc[8];
  #pragma unroll
  for(int n=0;n<8;n++) wmma::fill_fragment(acc[n], 0.0f);

  #pragma unroll
  for(int k=0;k<DD;k+=16){
    wmma::fragment<wmma::matrix_a,16,16,16,__nv_bfloat16,wmma::row_major> af;
    wmma::load_matrix_sync(af, As + (warp*16)*LDAB + k, LDAB);
    #pragma unroll
    for(int n=0;n<8;n++){
      wmma::fragment<wmma::matrix_b,16,16,16,__nv_bfloat16,wmma::row_major> bf;
      wmma::load_matrix_sync(bf, Bs + k*LDAB + n*16, LDAB);
      wmma::mma_sync(acc[n], af, bf, acc[n]);
    }
  }
  __syncthreads();   // done with Bs; reuse as epilogue buffers

  float* epi = (float*)Bs + warp*320;   // 16x20 floats per warp; 16 warps x 1280B = 20480B <= 34816B
  int r2=lane>>1, half=lane&1;
  float nw = nw_s[warp*16+r2];
  float v=0.f;
  #pragma unroll
  for(int n=0;n<8;n++){
    wmma::store_matrix_sync(epi, acc[n], 20, wmma::mem_row_major);
    __syncwarp();
    const float* crow = epi + r2*20 + half*8;
    int cb = n*16 + half*8;
    #pragma unroll
    for(int j=0;j<8;j++){
      float t = crow[j] + nw*wl_s[cb+j];
      t = (t>0.f)?t:(LEAKC*t);
      v = fmaf(t, w2_s[cb+j], v);
    }
    __syncwarp();
  }
  v += __shfl_xor_sync(0xffffffffu, v, 1);
  int rg = row0 + warp*16 + r2;
  if(half==0 && rg<7200) logits[(size_t)b*7200 + rg] = v;
}

// ---------------- k_soft_agg_f: softmax over 12 logits + fused W3 via E3 tables -> out1 ----------------
__global__ void __launch_bounds__(32) k_soft_agg_f(
    const int* __restrict__ inputs, const int* __restrict__ adj_all,
    const float* __restrict__ logits)
{
  const int N = 600;
  int blk=blockIdx.x; int b=blk/N; int i=blk-b*N; int tid=threadIdx.x;
  __shared__ int   ci_s[SAMP];
  __shared__ float lg_s[SAMP];
  int pi=i/SAMP, ps=i-pi*SAMP;
  int node = adj_all[inputs[b*SS+pi]*SAMP+ps];
  if(tid<SAMP){
    ci_s[tid] = adj_all[node*SAMP+tid];
    lg_s[tid] = logits[(size_t)b*7200 + i*SAMP + tid];
  }
  __syncwarp();
  float lg[SAMP];
  #pragma unroll
  for(int s=0;s<SAMP;s++) lg[s]=lg_s[s];
  float m=-1e30f;
  #pragma unroll
  for(int s=0;s<SAMP;s++) m=fmaxf(m,lg[s]);
  float alpha[SAMP]; float den=0.f;
  #pragma unroll
  for(int s=0;s<SAMP;s++){ alpha[s]=expf(lg[s]-m); den+=alpha[s]; }
  float inv=1.f/den;
  float4 t4 = ((const float4*)&g_E3top[(size_t)node*DD])[tid];
  float a0=0.f,a1=0.f,a2=0.f,a3=0.f;
  #pragma unroll
  for(int s=0;s<SAMP;s++){
    float4 e4 = ((const float4*)&g_E3bot[(size_t)ci_s[s]*DD])[tid];
    float al = alpha[s];
    a0=fmaf(al,e4.x,a0); a1=fmaf(al,e4.y,a1); a2=fmaf(al,e4.z,a2); a3=fmaf(al,e4.w,a3);
  }
  float4 o;
  o.x = tanhf(t4.x + a0*inv);
  o.y = tanhf(t4.y + a1*inv);
  o.z = tanhf(t4.z + a2*inv);
  o.w = tanhf(t4.w + a3*inv);
  ((float4*)&g_out1[(size_t)blk*DD])[tid] = o;
}

// ---------------- k_gemm3: out = tanh(cat @ W3), tiled 32 rows x 128 cols (modes 0/2) ----------------
__global__ void __launch_bounds__(128) k_gemm3(const float* __restrict__ w3,
                                               float* __restrict__ out){
  int row0 = blockIdx.x*32; int tid=threadIdx.x;
  int c = tid;
  __shared__ __align__(16) float As[16][32];
  float acc[32];
  #pragma unroll
  for(int r=0;r<32;r++) acc[r]=0.f;
  int rld = tid & 31;
  int kq  = tid >> 5;
  for(int k0=0;k0<2*DD;k0+=16){
    float4 av = *(const float4*)&g_cat[(size_t)(row0+rld)*2*DD + k0 + kq*4];
    As[kq*4+0][rld]=av.x; As[kq*4+1][rld]=av.y; As[kq*4+2][rld]=av.z; As[kq*4+3][rld]=av.w;
    __syncthreads();
    const float* w3c = w3 + (size_t)k0*DD + c;
    #pragma unroll 4
    for(int k=0;k<16;k++){
      float bk = w3c[k*DD];
      #pragma unroll
      for(int r4=0;r4<8;r4++){
        float4 a = *(const float4*)&As[k][r4*4];
        acc[r4*4+0]=fmaf(a.x,bk,acc[r4*4+0]);
        acc[r4*4+1]=fmaf(a.y,bk,acc[r4*4+1]);
        acc[r4*4+2]=fmaf(a.z,bk,acc[r4*4+2]);
        acc[r4*4+3]=fmaf(a.w,bk,acc[r4*4+3]);
      }
    }
    __syncthreads();
  }
  #pragma unroll
  for(int r=0;r<32;r++)
    out[(size_t)(row0+r)*DD + c] = tanhf(acc[r]);
}

// ---------------- k_attx ----------------
__global__ void k_attx(const int* __restrict__ adj, const float* __restrict__ a_local){
  int b=blockIdx.x; int tid=threadIdx.x;  // 256 threads
  __shared__ __align__(16) float xs[SS][DD+4];
  __shared__ __align__(16) float al_s[4][DD];
  __shared__ float att[SS][SS+2];
  for(int idx=tid; idx<SS*DD; idx+=256){
    int i=idx>>7, d=idx&127;
    xs[i][d]=g_x[(b*SS+i)*DD+d];
  }
  for(int idx=tid; idx<4*DD; idx+=256)
    al_s[idx>>7][idx&127]=a_local[idx];
  __syncthreads();
  for(int p=tid;p<SS*SS;p+=256){
    int i=p/SS, j=p-i*SS;
    int k=adj[b*SS*SS+p];
    float e=-9e15f;
    if(k>=1 && k<=4){
      const float* al = al_s[k-1];
      float ds=0.f;
      #pragma unroll 8
      for(int d=0;d<DD;d+=4){
        float4 xi=*(const float4*)&xs[i][d];
        float4 xj=*(const float4*)&xs[j][d];
        float4 av=*(const float4*)&al[d];
        ds += xi.x*xj.x*av.x + xi.y*xj.y*av.y + xi.z*xj.z*av.z + xi.w*xj.w*av.w;
      }
      e = (ds>0.f)?ds:(LEAKC*ds);
    }
    att[i][j]=e;
  }
  __syncthreads();
  if(tid<SS){
    float m=-1e30f;
    for(int j=0;j<SS;j++) m=fmaxf(m,att[tid][j]);
    float den=0.f;
    for(int j=0;j<SS;j++){ float e=expf(att[tid][j]-m); att[tid][j]=e; den+=e; }
    float inv=1.f/den;
    for(int j=0;j<SS;j++) att[tid][j]*=inv;
  }
  __syncthreads();
  for(int q=tid;q<SS*DD;q+=256){
    int i=q>>7, d=q&127;
    float acc=0.f;
    for(int j=0;j<SS;j++) acc += att[i][j]*xs[j][d];
    g_xnew[(b*SS+i)*DD+d]=acc;
  }
}

// ---------------- k_gate ----------------
__global__ void k_gate(const float* __restrict__ w1, const float* __restrict__ w2){
  int blk=blockIdx.x, tid=threadIdx.x;
  __shared__ __align__(16) float xn[DD], mr[DD];
  xn[tid]=g_xnew[blk*DD+tid]; mr[tid]=g_mirror[blk*DD+tid];
  __syncthreads();
  const float* w1t=w1+tid; const float* w2t=w2+tid;
  float acc=0.f;
  #pragma unroll 8
  for(int k=0;k<DD;k+=4){
    float4 x4=*(const float4*)&xn[k];
    float4 m4=*(const float4*)&mr[k];
    acc=fmaf(x4.x,w1t[(k  )*DD],acc); acc=fmaf(m4.x,w2t[(k  )*DD],acc);
    acc=fmaf(x4.y,w1t[(k+1)*DD],acc); acc=fmaf(m4.y,w2t[(k+1)*DD],acc);
    acc=fmaf(x4.z,w1t[(k+2)*DD],acc); acc=fmaf(m4.z,w2t[(k+2)*DD],acc);
    acc=fmaf(x4.w,w1t[(k+3)*DD],acc); acc=fmaf(m4.w,w2t[(k+3)*DD],acc);
  }
  float gm=sigm(acc);
  float xv=xn[tid], mv=mr[tid];
  g_x[blk*DD+tid]     = gm*xv + (1.f-gm)*mv;
  g_mirror[blk*DD+tid]= gm*mv + (1.f-gm)*xv;
}

// ---------------- k_highway ----------------
__global__ void k_highway(const float* __restrict__ hw){
  int blk=blockIdx.x, tid=threadIdx.x;
  __shared__ __align__(16) float hr[DD], xr[DD];
  hr[tid]=g_h[blk*DD+tid]; xr[tid]=g_x[blk*DD+tid];
  __syncthreads();
  const float* wt=hw+tid;
  float acc=0.f;
  #pragma unroll 8
  for(int k=0;k<DD;k+=4){
    float4 h4=*(const float4*)&hr[k];
    float4 x4=*(const float4*)&xr[k];
    acc=fmaf(h4.x,wt[(k  )*DD],acc); acc=fmaf(x4.x,wt[(DD+k  )*DD],acc);
    acc=fmaf(h4.y,wt[(k+1)*DD],acc); acc=fmaf(x4.y,wt[(DD+k+1)*DD],acc);
    acc=fmaf(h4.z,wt[(k+2)*DD],acc); acc=fmaf(x4.z,wt[(DD+k+2)*DD],acc);
    acc=fmaf(h4.w,wt[(k+3)*DD],acc); acc=fmaf(x4.w,wt[(DD+k+3)*DD],acc);
  }
  float g=sigm(acc);
  float xd=g*hr[tid]+(1.f-g)*xr[tid];
  g_xdot[blk*DD+tid]=xd;
  int s=blk%SS;
  if(s==SS-1) g_hlocal[(blk/SS)*DD+tid]=xd;
}

// ---------------- k_hs ----------------
__global__ void k_hs(const int* __restrict__ inputs){
  int b=blockIdx.x, tid=threadIdx.x;
  float acc=0.f, cnt=0.f;
  for(int s=0;s<SS;s++){
    if(inputs[b*SS+s]!=0){ acc += g_hglob[(b*SS+s)*DD+tid]; cnt+=1.f; }
  }
  g_hs[b*DD+tid]=acc/cnt;
}

// ---------------- k_c2 ----------------
__global__ void k_c2(const float* __restrict__ glu2, const float* __restrict__ glu4,
                     const float* __restrict__ glu4b){
  int b=blockIdx.x, tid=threadIdx.x;
  __shared__ __align__(16) float hsr[DD], hlr[DD];
  hsr[tid]=g_hs[b*DD+tid]; hlr[tid]=g_hlocal[b*DD+tid];
  __syncthreads();
  float acc=glu4b[tid];
  const float* w2t=glu2+tid; const float* w4t=glu4+tid;
  #pragma unroll 8
  for(int k=0;k<DD;k+=4){
    float4 s4=*(const float4*)&hsr[k];
    float4 l4=*(const float4*)&hlr[k];
    acc=fmaf(s4.x,w2t[(k  )*DD],acc); acc=fmaf(l4.x,w4t[(k  )*DD],acc);
    acc=fmaf(s4.y,w2t[(k+1)*DD],acc); acc=fmaf(l4.y,w4t[(k+1)*DD],acc);
    acc=fmaf(s4.z,w2t[(k+2)*DD],acc); acc=fmaf(l4.z,w4t[(k+2)*DD],acc);
    acc=fmaf(s4.w,w2t[(k+3)*DD],acc); acc=fmaf(l4.w,w4t[(k+3)*DD],acc);
  }
  g_c2[b*DD+tid]=acc;
}

// ---------------- k_beta ----------------
__global__ void k_beta(const int* __restrict__ inputs, const float* __restrict__ pos,
                       const float* __restrict__ glu1, const float* __restrict__ ws){
  int blk=blockIdx.x, tid=threadIdx.x;
  int s=blk%SS, b=blk/SS;
  __shared__ __align__(16) float hp[DD];
  __shared__ float red[DD];
  hp[tid]=g_xdot[blk*DD+tid] + pos[s*DD+tid];
  __syncthreads();
  const float* wt=glu1+tid;
  float acc=0.f;
  #pragma unroll 8
  for(int k=0;k<DD;k+=4){
    float4 h4=*(const float4*)&hp[k];
    acc=fmaf(h4.x,wt[(k  )*DD],acc); acc=fmaf(h4.y,wt[(k+1)*DD],acc);
    acc=fmaf(h4.z,wt[(k+2)*DD],acc); acc=fmaf(h4.w,wt[(k+3)*DD],acc);
  }
  float nh=sigm(acc + g_c2[b*DD+tid]);
  red[tid]=nh*ws[tid];
  __syncthreads();
  for(int off=64;off>0;off>>=1){ if(tid<off) red[tid]+=red[tid+off]; __syncthreads(); }
  if(tid==0){
    float mi=(inputs[blk]!=0)?1.f:0.f;
    g_beta[blk]=red[0]*mi;
  }
}

// ---------------- k_zg ----------------
__global__ void k_zg(const float* __restrict__ pos){
  int b=blockIdx.x, tid=threadIdx.x;
  float acc=0.f;
  for(int s=0;s<SS;s++)
    acc += g_beta[b*SS+s]*(g_xdot[(b*SS+s)*DD+tid]+pos[s*DD+tid]);
  g_zg[b*DD+tid]=acc;
}

// ---------------- k_zh ----------------
__global__ void k_zh(const float* __restrict__ gatew){
  int b=blockIdx.x, tid=threadIdx.x;
  __shared__ __align__(16) float zgr[DD], hlr[DD];
  zgr[tid]=g_zg[b*DD+tid]; hlr[tid]=g_hlocal[b*DD+tid];
  __syncthreads();
  const float* wt=gatew+tid;
  float acc=0.f;
  #pragma unroll 8
  for(int k=0;k<DD;k+=4){
    float4 z4=*(const float4*)&zgr[k];
    float4 l4=*(const float4*)&hlr[k];
    acc=fmaf(z4.x,wt[(k  )*DD],acc); acc=fmaf(l4.x,wt[(DD+k  )*DD],acc);
    acc=fmaf(z4.y,wt[(k+1)*DD],acc); acc=fmaf(l4.y,wt[(DD+k+1)*DD],acc);
    acc=fmaf(z4.z,wt[(k+2)*DD],acc); acc=fmaf(l4.z,wt[(DD+k+2)*DD],acc);
    acc=fmaf(z4.w,wt[(k+3)*DD],acc); acc=fmaf(l4.w,wt[(DD+k+3)*DD],acc);
  }
  float gf=sigm(acc)*0.1f;
  float zh=gf*hlr[tid]+(1.f-gf)*zgr[tid];
  g_zhT[tid*BB+b]=zh;
}

// ---------------- k_scores ----------------
__global__ void k_scores(const float* __restrict__ emb, float* __restrict__ out){
  int n0 = blockIdx.x*32; int tid=threadIdx.x;
  __shared__ __align__(16) float es[32][DD];
  int nmax = NSCORE - n0; if(nmax>32) nmax=32;
  for(int idx=tid; idx<nmax*DD; idx+=128){
    int nn=idx>>7, d=idx&127;
    es[nn][d]=emb[(size_t)(n0+nn+1)*DD+d];
  }
  __syncthreads();
  float accv[32];
  #pragma unroll
  for(int nn=0;nn<32;nn++) accv[nn]=0.f;
  for(int d=0;d<DD;d+=4){
    float z0=g_zhT[(d  )*BB+tid];
    float z1=g_zhT[(d+1)*BB+tid];
    float z2=g_zhT[(d+2)*BB+tid];
    float z3=g_zhT[(d+3)*BB+tid];
    #pragma unroll
    for(int nn=0;nn<32;nn++){
      float4 e=*reinterpret_cast<const float4*>(&es[nn][d]);
      accv[nn]=fmaf(z0,e.x,fmaf(z1,e.y,fmaf(z2,e.z,fmaf(z3,e.w,accv[nn]))));
    }
  }
  for(int nn=0;nn<nmax;nn++)
    out[1 + (size_t)tid*NSCORE + n0+nn] = accv[nn];
}

// ---------------- k_simi ----------------
__global__ void k_simi(const int* __restrict__ simi_mask){
  int blk=blockIdx.x; int b=blk/SS; int tid=threadIdx.x; // 64 threads
  __shared__ float f1[DD];
  __shared__ float sims[SS];
  f1[tid]   =g_hf1[blk*DD+tid];
  f1[tid+64]=g_hf1[blk*DD+tid+64];
  __syncthreads();
  if(tid<SS){
    const float* f2=&g_hf2[(b*SS+tid)*DD];
    float acc=0.f;
    for(int d=0;d<DD;d++) acc+=f1[d]*f2[d];
    sims[tid]=acc*2.0f;   // 1/TEMP
  }
  __syncthreads();
  if(tid==0){
    float m=-1e30f;
    for(int j=0;j<SS;j++) m=fmaxf(m,sims[j]);
    float den=0.f;
    for(int j=0;j<SS;j++) den+=expf(sims[j]-m);
    float loss=0.f;
    for(int j=0;j<SS;j++){
      float p=expf(sims[j]-m)/den;
      float l=-logf(p+1e-8f);
      if(simi_mask[blk*SS+j]==1) loss+=l;
    }
    g_partial[blk]=loss;
  }
}

__global__ void k_simi_final(float* __restrict__ out){
  int tid=threadIdx.x; // 128
  __shared__ float red[128];
  float a=0.f;
  for(int i=tid;i<BB*SS;i+=128) a+=g_partial[i];
  red[tid]=a; __syncthreads();
  for(int off=64;off>0;off>>=1){ if(tid<off) red[tid]+=red[tid+off]; __syncthreads(); }
  if(tid==0) out[0]=red[0]/(float)BB;
}

// ---------------- launch ----------------
extern "C" void kernel_launch(void* const* d_in, const int* in_sizes, int n_in,
                              void* d_out, int out_size){
  const int*   inputs =(const int*)  d_in[0];
  const int*   adj    =(const int*)  d_in[1];
  const int*   item   =(const int*)  d_in[2];
  const int*   simi   =(const int*)  d_in[3];
  const int*   as0    =(const int*)  d_in[4];
  const int*   as1    =(const int*)  d_in[5];
  const int*   ssl0   =(const int*)  d_in[6];
  const int*   ssl1   =(const int*)  d_in[7];
  // d_in[8] = last_item_mask (statically [:, -1]; unused)
  const int*   adj_all=(const int*)  d_in[9];
  const float* num    =(const float*)d_in[10];
  const float* emb    =(const float*)d_in[11];
  const float* pos    =(const float*)d_in[12];
  const float* a_local=(const float*)d_in[13];
  const float* mir1   =(const float*)d_in[14];
  const float* mir2   =(const float*)d_in[15];
  const float* gw1    =(const float*)d_in[16];
  const float* gw2    =(const float*)d_in[17];
  const float* gw3    =(const float*)d_in[18];
  const float* attr   =(const float*)d_in[19];
  const float* hww    =(const float*)d_in[20];
  const float* glu1   =(const float*)d_in[21];
  const float* glu2   =(const float*)d_in[22];
  const float* glu4   =(const float*)d_in[23];
  const float* glu4b  =(const float*)d_in[24];
  const float* ws     =(const float*)d_in[25];
  const float* gatew  =(const float*)d_in[26];
  float* out=(float*)d_out;

  float* p_out0;   cudaGetSymbolAddress((void**)&p_out0,  g_out0);
  float* p_hglob;  cudaGetSymbolAddress((void**)&p_hglob, g_hglob);
  float* p_logits; cudaGetSymbolAddress((void**)&p_logits,g_logits);

  const int LOGITS_SMEM = 69632 + 34816 + (3*DD + LROWS)*4 + LROWS*4;  // 108032 B
  cudaFuncSetAttribute(k_logits, cudaFuncAttributeMaxDynamicSharedMemorySize, LOGITS_SMEM);

  k_w1bf<<<DD*DD/256,256>>>(gw1);
  k_e3<<<NNODE/32,128>>>(emb, gw3);          // E3 tables for modes 0/1 (hop-0 w3)
  k_pool<<<BB*SS,DD>>>(inputs, as0, as1, ssl0, ssl1, emb);
  k_attr<<<BB*SS,DD>>>(attr);
  k_sess<<<BB,DD>>>(inputs,item,emb);

  // mode 1: bf16 TC logits -> fused softmax/agg/W3 via E3 -> out1
  {
    dim3 g((7200+LROWS-1)/LROWS, BB);   // 29 x 128
    k_logits<<<g,512,LOGITS_SMEM>>>(inputs,adj_all,num, emb, gw1+DD*DD, gw2, p_logits);
  }
  k_soft_agg_f<<<BB*600,32>>>(inputs,adj_all, p_logits);

  // mode 0: scalar fused path (hop-0 weights) + small gemm3
  k_att<<<BB*SS,32>>>(inputs,adj_all,num, emb, gw1, gw2, SS, 0);
  k_gemm3<<<BB*SS/32,128>>>(gw3, p_out0);

  // mode 2: scalar fused path (hop-1 weights) + small gemm3
  k_att<<<BB*SS,32>>>(inputs,adj_all,num, emb, gw1+129*DD, gw2+DD, SS, 2);
  k_gemm3<<<BB*SS/32,128>>>(gw3+256*DD, p_hglob);

  // local branch: 2 iterations
  for(int it=0; it<2; it++){
    k_attx<<<BB,256>>>(adj, a_local + it*4*DD);
    k_gate<<<BB*SS,DD>>>(mir1 + it*DD*DD, mir2 + it*DD*DD);
  }
  k_highway<<<BB*SS,DD>>>(hww);
  k_hs<<<BB,DD>>>(inputs);
  k_c2<<<BB,DD>>>(glu2,glu4,glu4b);
  k_beta<<<BB*SS,DD>>>(inputs,pos,glu1,ws);
  k_zg<<<BB,DD>>>(pos);
  k_zh<<<BB,DD>>>(gatew);

  k_scores<<<(NSCORE+31)/32,128>>>(emb,out);
  k_simi<<<BB*SS,64>>>(simi);
  k_simi_final<<<1,128>>>(out);
}